// round 1
// baseline (speedup 1.0000x reference)
#include <cuda_runtime.h>
#include <math.h>

#define B_BATCH 4096
#define HID     512
#define G4      2048   // 4*HID

// ---------------- device scratch (no allocations allowed) ----------------
__device__ float g_E[9 * G4];                 // emb @ w_ih^T + b_ih + b_hh  [9, 2048]
__device__ float g_h[2][B_BATCH * HID];       // ping-pong hidden state
__device__ float g_c[B_BATCH * HID];          // cell state
__device__ int   g_tok[B_BATCH];              // current input token per row

typedef unsigned long long ull;

__device__ __forceinline__ ull pack2same(float x){
    ull r; asm("mov.b64 %0, {%1, %1};" : "=l"(r) : "f"(x)); return r;
}
__device__ __forceinline__ float2 unpack2(ull v){
    float2 r; asm("mov.b64 {%0, %1}, %2;" : "=f"(r.x), "=f"(r.y) : "l"(v)); return r;
}
__device__ __forceinline__ ull fma2(ull a, ull b, ull c){
    ull d; asm("fma.rn.f32x2 %0, %1, %2, %3;" : "=l"(d) : "l"(a), "l"(b), "l"(c)); return d;
}
__device__ __forceinline__ float sigmoidf_(float x){ return 1.0f / (1.0f + expf(-x)); }

// ---------------- init: zero h0, c, tokens ----------------
__global__ void init_kernel(){
    int idx = blockIdx.x * blockDim.x + threadIdx.x;
    int stride = gridDim.x * blockDim.x;
    for (int i = idx; i < B_BATCH * HID; i += stride){ g_h[0][i] = 0.0f; g_c[i] = 0.0f; }
    if (idx < B_BATCH) g_tok[idx] = 0;
}

// ---------------- E = emb @ w_ih^T + b_ih + b_hh ----------------
__global__ void precompute_E(const float* __restrict__ emb,
                             const float* __restrict__ w_ih,
                             const float* __restrict__ b_ih,
                             const float* __restrict__ b_hh){
    __shared__ float er[HID];
    int t = blockIdx.y;                          // token 0..8
    int j = blockIdx.x * blockDim.x + threadIdx.x; // gate col 0..2047
    for (int k = threadIdx.x; k < HID; k += blockDim.x) er[k] = emb[t * HID + k];
    __syncthreads();
    const float* w = w_ih + (size_t)j * HID;
    float s = 0.f;
    #pragma unroll 4
    for (int k = 0; k < HID; k += 4){
        float4 wv = *(const float4*)(w + k);
        s += er[k]*wv.x + er[k+1]*wv.y + er[k+2]*wv.z + er[k+3]*wv.w;
    }
    g_E[t * G4 + j] = s + b_ih[j] + b_hh[j];
}

// ---------------- fused GEMM (h @ w_hh^T) + embedding gather + LSTM pointwise ---------
// Block tile: 128 rows x 32 h-cols -> 128 gate-cols (all 4 gates of the 32 cols).
// Threads 256 = 16 (cx: h-col pairs) x 16 (ry: 8-row groups).
// Per-thread micro-tile: 8 rows x (2 h-cols x 4 gates) via packed f32x2 FMAs.
#define BM 128
#define BH 32
#define BN 128
#define BK 16
#define NCHUNK (HID / BK)

__global__ __launch_bounds__(256, 2)
void lstm_step_kernel(const float* __restrict__ w_hh, int phase){
    __shared__ __align__(16) float As[2][BK][BM];
    __shared__ __align__(16) float Bs[2][BK][BN];
    __shared__ float Es[9][BN];
    __shared__ int toks[BM];

    const float* __restrict__ hin  = g_h[phase];
    float*       __restrict__ hout = g_h[phase ^ 1];

    int tid = threadIdx.x;
    int cx  = tid & 15;     // 0..15 -> h-cols {2cx, 2cx+1}
    int ry  = tid >> 4;     // 0..15 -> rows ry*8..ry*8+7
    int H0  = blockIdx.x * BH;
    int R0  = blockIdx.y * BM;

    if (tid < BM) toks[tid] = g_tok[R0 + tid];
    for (int idx = tid; idx < 9 * BN; idx += 256){
        int t  = idx >> 7;
        int gc = idx & 127;
        Es[t][gc] = g_E[t * G4 + (gc >> 5) * HID + H0 + (gc & 31)];
    }

    // global -> smem loader mapping (each thread: 2x float4 for A, 2x float4 for B)
    int arow = tid >> 1;                // 0..127
    int kseg = (tid & 1) << 3;          // 0 or 8
    const float* Ag = hin + (size_t)(R0 + arow) * HID + kseg;
    int gc_l = tid >> 1;                // gate-col 0..127
    const float* Bg = w_hh + (size_t)((gc_l >> 5) * HID + H0 + (gc_l & 31)) * HID + kseg;

    float4 a0 = *(const float4*)(Ag);
    float4 a1 = *(const float4*)(Ag + 4);
    float4 b0 = *(const float4*)(Bg);
    float4 b1 = *(const float4*)(Bg + 4);
    #pragma unroll
    for (int q = 0; q < 4; ++q){
        As[0][kseg + q][arow]     = ((const float*)&a0)[q];
        As[0][kseg + 4 + q][arow] = ((const float*)&a1)[q];
        Bs[0][kseg + q][gc_l]     = ((const float*)&b0)[q];
        Bs[0][kseg + 4 + q][gc_l] = ((const float*)&b1)[q];
    }
    __syncthreads();

    ull acc[8][4];
    #pragma unroll
    for (int r = 0; r < 8; ++r)
        #pragma unroll
        for (int g = 0; g < 4; ++g) acc[r][g] = 0ULL;

    for (int c = 0; c < NCHUNK; ++c){
        int cur = c & 1;
        if (c + 1 < NCHUNK){
            const float* Agn = Ag + (c + 1) * BK;
            const float* Bgn = Bg + (c + 1) * BK;
            a0 = *(const float4*)(Agn);
            a1 = *(const float4*)(Agn + 4);
            b0 = *(const float4*)(Bgn);
            b1 = *(const float4*)(Bgn + 4);
        }
        const float (*Asc)[BM] = As[cur];
        const ull* Bsc = (const ull*)&Bs[cur][0][0];   // [BK][BN/2] as f32x2 pairs
        #pragma unroll
        for (int kk = 0; kk < BK; ++kk){
            ull bp[4];
            #pragma unroll
            for (int g = 0; g < 4; ++g) bp[g] = Bsc[kk * (BN/2) + g * 16 + cx];
            #pragma unroll
            for (int r = 0; r < 8; ++r){
                ull ap = pack2same(Asc[kk][ry * 8 + r]);
                #pragma unroll
                for (int g = 0; g < 4; ++g) acc[r][g] = fma2(ap, bp[g], acc[r][g]);
            }
        }
        if (c + 1 < NCHUNK){
            int nxt = cur ^ 1;
            #pragma unroll
            for (int q = 0; q < 4; ++q){
                As[nxt][kseg + q][arow]     = ((const float*)&a0)[q];
                As[nxt][kseg + 4 + q][arow] = ((const float*)&a1)[q];
                Bs[nxt][kseg + q][gc_l]     = ((const float*)&b0)[q];
                Bs[nxt][kseg + 4 + q][gc_l] = ((const float*)&b1)[q];
            }
            __syncthreads();
        }
    }

    // epilogue: add gathered E, LSTM pointwise, write h/c
    int hc = cx << 1;
    #pragma unroll
    for (int r = 0; r < 8; ++r){
        int lrow = ry * 8 + r;
        int t = toks[lrow];
        float2 iv = unpack2(acc[r][0]);
        float2 fv = unpack2(acc[r][1]);
        float2 gv = unpack2(acc[r][2]);
        float2 ov = unpack2(acc[r][3]);
        iv.x += Es[t][hc];      iv.y += Es[t][hc + 1];
        fv.x += Es[t][32 + hc]; fv.y += Es[t][32 + hc + 1];
        gv.x += Es[t][64 + hc]; gv.y += Es[t][64 + hc + 1];
        ov.x += Es[t][96 + hc]; ov.y += Es[t][96 + hc + 1];
        size_t base = (size_t)(R0 + lrow) * HID + H0 + hc;
        float2 cold = *(const float2*)&g_c[base];
        float ix = sigmoidf_(iv.x), iy = sigmoidf_(iv.y);
        float fx = sigmoidf_(fv.x), fy = sigmoidf_(fv.y);
        float gx = tanhf(gv.x),     gy = tanhf(gv.y);
        float ox = sigmoidf_(ov.x), oy = sigmoidf_(ov.y);
        float cnx = fx * cold.x + ix * gx;
        float cny = fy * cold.y + iy * gy;
        float2 cn; cn.x = cnx; cn.y = cny;
        float2 hn; hn.x = ox * tanhf(cnx); hn.y = oy * tanhf(cny);
        *(float2*)&g_c[base]  = cn;
        *(float2*)&hout[base] = hn;
    }
}

// ---------------- decision heads + gumbel-max sampling ----------------
// One warp per batch row. k node logits (tanh-squashed) + 8 op logits.
__global__ __launch_bounds__(256)
void decide_kernel(int phase_out,
                   const float* __restrict__ wn, const float* __restrict__ bn, int k,
                   const float* __restrict__ wop, const float* __restrict__ bop,
                   const float* __restrict__ gum, int s, float* __restrict__ out){
    __shared__ float wns[5 * HID];
    __shared__ float wos[8 * HID];
    __shared__ float bns[5];
    __shared__ float bos[8];
    const float* h = g_h[phase_out];
    int tid = threadIdx.x;
    for (int idx = tid; idx < 5 * HID; idx += 256) wns[idx] = (idx < k * HID) ? wn[idx] : 0.0f;
    for (int idx = tid; idx < 8 * HID; idx += 256) wos[idx] = wop[idx];
    if (tid < 5) bns[tid] = (tid < k) ? bn[tid] : 0.0f;
    if (tid < 8) bos[tid] = bop[tid];
    __syncthreads();

    int wid = tid >> 5, lane = tid & 31;
    int b = blockIdx.x * 8 + wid;
    const float* hr = h + (size_t)b * HID;
    float dn[5] = {0,0,0,0,0};
    float dq[8] = {0,0,0,0,0,0,0,0};
    #pragma unroll
    for (int j = 0; j < 16; ++j){
        int col = lane + (j << 5);
        float hv = hr[col];
        #pragma unroll
        for (int w = 0; w < 5; ++w) dn[w] += hv * wns[w * HID + col];
        #pragma unroll
        for (int w = 0; w < 8; ++w) dq[w] += hv * wos[w * HID + col];
    }
    #pragma unroll
    for (int off = 16; off > 0; off >>= 1){
        #pragma unroll
        for (int w = 0; w < 5; ++w) dn[w] += __shfl_xor_sync(0xffffffffu, dn[w], off);
        #pragma unroll
        for (int w = 0; w < 8; ++w) dq[w] += __shfl_xor_sync(0xffffffffu, dq[w], off);
    }
    if (lane == 0){
        float l[8];
        // ---- node decision -> output row 2s ----
        for (int w = 0; w < k; ++w) l[w] = 2.5f * tanhf((dn[w] + bns[w]) * 0.2f);
        {
            const float* g0 = gum + ((size_t)(2 * s) * B_BATCH + b) * 8;
            float m = l[0]; for (int w = 1; w < k; ++w) m = fmaxf(m, l[w]);
            float sum = 0.f; for (int w = 0; w < k; ++w) sum += expf(l[w] - m);
            float lse = m + logf(sum);
            float ent = 0.f;
            for (int w = 0; w < k; ++w){ float lp = l[w] - lse; ent -= lp * expf(lp); }
            int a = 0; float best = l[0] + g0[0];
            for (int w = 1; w < k; ++w){ float v = l[w] + g0[w]; if (v > best){ best = v; a = w; } }
            int row = 2 * s;
            out[(size_t)row * B_BATCH + b]        = (float)a;
            out[(size_t)(16 + row) * B_BATCH + b] = l[a] - lse;
            out[(size_t)(32 + row) * B_BATCH + b] = ent;
        }
        // ---- op decision -> output row 2s+1, feeds next token ----
        for (int w = 0; w < 8; ++w) l[w] = (dq[w] + bos[w]) * 0.2f;
        {
            const float* g1 = gum + ((size_t)(2 * s + 1) * B_BATCH + b) * 8;
            float m = l[0]; for (int w = 1; w < 8; ++w) m = fmaxf(m, l[w]);
            float sum = 0.f; for (int w = 0; w < 8; ++w) sum += expf(l[w] - m);
            float lse = m + logf(sum);
            float ent = 0.f;
            for (int w = 0; w < 8; ++w){ float lp = l[w] - lse; ent -= lp * expf(lp); }
            int a = 0; float best = l[0] + g1[0];
            for (int w = 1; w < 8; ++w){ float v = l[w] + g1[w]; if (v > best){ best = v; a = w; } }
            int row = 2 * s + 1;
            out[(size_t)row * B_BATCH + b]        = (float)a;
            out[(size_t)(16 + row) * B_BATCH + b] = l[a] - lse;
            out[(size_t)(32 + row) * B_BATCH + b] = ent;
            g_tok[b] = a;
        }
    }
}

// ---------------- launch ----------------
extern "C" void kernel_launch(void* const* d_in, const int* in_sizes, int n_in,
                              void* d_out, int out_size){
    const float* emb  = (const float*)d_in[0];
    const float* w_ih = (const float*)d_in[1];
    const float* w_hh = (const float*)d_in[2];
    const float* b_ih = (const float*)d_in[3];
    const float* b_hh = (const float*)d_in[4];
    const float* wn[4] = {(const float*)d_in[5], (const float*)d_in[7],
                          (const float*)d_in[9], (const float*)d_in[11]};
    const float* bn[4] = {(const float*)d_in[6], (const float*)d_in[8],
                          (const float*)d_in[10], (const float*)d_in[12]};
    const float* wop = (const float*)d_in[13];
    const float* bop = (const float*)d_in[14];
    const float* gum = (const float*)d_in[15];
    float* out = (float*)d_out;

    init_kernel<<<1024, 256>>>();
    precompute_E<<<dim3(G4 / 256, 9), 256>>>(emb, w_ih, b_ih, b_hh);
    for (int s = 0; s < 8; ++s){
        int i = s >> 1;
        lstm_step_kernel<<<dim3(HID / BH, B_BATCH / BM), 256>>>(w_hh, s & 1);
        decide_kernel<<<B_BATCH / 8, 256>>>((s + 1) & 1, wn[i], bn[i], i + 2,
                                            wop + (size_t)i * 8 * HID, bop + i * 8,
                                            gum, s, out);
    }
}